// round 13
// baseline (speedup 1.0000x reference)
#include <cuda_runtime.h>
#include <cuda.h>
#include <cuda_bf16.h>
#include <cstdint>

// Correlation layer (FlowNet-style), MAX_DISP=4.
// first, second: (B=4, C=256, H=128, W=224) fp32 NCHW
// out: (B, 81, H, W) fp32
//
// R12: XPT=8 + pixel-paired fma.rn.f32x2.
//      Threads = (tx4, dy9, ly4, csplit2) = 288, all active.
//      TMA double buffer, CC=16 (each half does 8 ch/chunk), SROW=44
//      (conflict-free), end-of-kernel smem reduction across the c-halves.

#define B_   4
#define C_   256
#define H_   128
#define W_   224
#define P_   4
#define D_   9      // 2P+1
#define ND_  81

#define TX    32    // x-tile width (224 = 7*32)
#define YT    4     // y rows per block
#define XPT   8     // x pixels per thread
#define XT    4     // x-thread count (32/8)
#define CC    16    // channels per chunk (8 per c-half)
#define CPH   8     // channels per half
#define NCHUNK (C_ / CC)   // 16

#define SWID  44    // second TMA box width: 8 halo + 32 + 4 right pad (OOB zero)
#define SROW  44    // == box width (dense TMA rows); 44 % 32 == 12 -> conflict-free
#define SH    12    // second rows incl. halo (4+8)
#define FROW  32

#define SCH   (SH * SROW)        // 528 floats per channel (second)
#define FCH   (YT * FROW)        // 128 floats per channel (first)
#define SBUF_FLOATS (CC * SCH)   // 8448
#define FBUF_FLOATS (CC * FCH)   // 2048
#define SBUF_BYTES  (SBUF_FLOATS * 4)   // 33792
#define FBUF_BYTES  (FBUF_FLOATS * 4)   // 8192
// layout: [S0][F0][S1][F1][mbar]  (buffer0 contiguous -> reusable as staging)
#define OFF_S0   0
#define OFF_F0   SBUF_BYTES
#define OFF_S1   (SBUF_BYTES + FBUF_BYTES)
#define OFF_F1   (2 * SBUF_BYTES + FBUF_BYTES)
#define OFF_MBAR (2 * SBUF_BYTES + 2 * FBUF_BYTES)   // 83968
#define SMEM_TOTAL (OFF_MBAR + 64)

#define CHUNK_TX_BYTES (SBUF_BYTES + FBUF_BYTES)     // 41984

#define NTHR 288    // 4 * 9 * 4 * 2, every thread is a worker
typedef unsigned long long u64;

// ---------------- device-side PTX helpers ----------------
__device__ __forceinline__ uint32_t smem_u32(const void* p) {
    return (uint32_t)__cvta_generic_to_shared(p);
}
__device__ __forceinline__ void mbar_init(uint32_t a, uint32_t cnt) {
    asm volatile("mbarrier.init.shared.b64 [%0], %1;" :: "r"(a), "r"(cnt) : "memory");
}
__device__ __forceinline__ void mbar_expect_tx(uint32_t a, uint32_t bytes) {
    asm volatile("mbarrier.arrive.expect_tx.shared.b64 _, [%0], %1;"
                 :: "r"(a), "r"(bytes) : "memory");
}
__device__ __forceinline__ void mbar_wait(uint32_t a, uint32_t parity) {
    uint32_t done;
    asm volatile(
        "{\n\t.reg .pred p;\n\t"
        "mbarrier.try_wait.parity.acquire.cta.shared::cta.b64 p, [%1], %2;\n\t"
        "selp.b32 %0, 1, 0, p;\n\t}"
        : "=r"(done) : "r"(a), "r"(parity) : "memory");
    if (!done) {
        asm volatile(
            "{\n\t.reg .pred P1;\n\t"
            "WL_%=:\n\t"
            "mbarrier.try_wait.parity.acquire.cta.shared::cta.b64 P1, [%0], %1, 0x989680;\n\t"
            "@P1 bra.uni WD_%=;\n\t"
            "bra.uni WL_%=;\n\t"
            "WD_%=:\n\t}"
            :: "r"(a), "r"(parity) : "memory");
    }
}
__device__ __forceinline__ void tma3d(uint32_t smem_dst, const CUtensorMap* tmap,
                                      int cx, int cy, int cz, uint32_t mbar) {
    asm volatile(
        "cp.async.bulk.tensor.3d.shared::cta.global.tile.mbarrier::complete_tx::bytes "
        "[%0], [%1, {%2, %3, %4}], [%5];"
        :: "r"(smem_dst), "l"(tmap), "r"(cx), "r"(cy), "r"(cz), "r"(mbar)
        : "memory");
}
__device__ __forceinline__ u64 pack2(float lo, float hi) {
    u64 r;
    asm("mov.b64 %0, {%1, %2};" : "=l"(r) : "f"(lo), "f"(hi));
    return r;
}
__device__ __forceinline__ void unpack2(float& lo, float& hi, u64 v) {
    asm("mov.b64 {%0, %1}, %2;" : "=f"(lo), "=f"(hi) : "l"(v));
}
__device__ __forceinline__ u64 fma2(u64 a, u64 b, u64 c) {
    u64 r;
    asm("fma.rn.f32x2 %0, %1, %2, %3;" : "=l"(r) : "l"(a), "l"(b), "l"(c));
    return r;
}

// ---------------- kernel ----------------
__global__ __launch_bounds__(NTHR, 2)
void corr_kernel(const __grid_constant__ CUtensorMap tm_first,
                 const __grid_constant__ CUtensorMap tm_second,
                 float* __restrict__ out)
{
    extern __shared__ float dyn[];
    const uint32_t smem_base = smem_u32(dyn);
    const uint32_t mbar0 = smem_base + OFF_MBAR;

    const int xt = blockIdx.x;          // 0..6
    const int y0 = blockIdx.y * YT;     // 0..124
    const int b  = blockIdx.z;          // 0..3
    const int x0 = xt * TX;

    const int tid = threadIdx.x;        // 0..287
    const int tx  = tid & 3;            // 0..3
    const int dy  = (tid >> 2) % D_;    // 0..8
    const int ly  = (tid / (XT * D_)) & 3;  // 0..3
    const int h   = tid / (XT * D_ * YT);   // 0..1  (channel half)
    const int w144 = tid % (XT * D_ * YT);  // id within a half, 0..143

    if (tid == 0) {
        mbar_init(mbar0, 1);
        mbar_init(mbar0 + 8, 1);
    }
    __syncthreads();

    // prefetch chunk 0 into buffer 0
    if (tid == 0) {
        const int cz = b * C_;
        mbar_expect_tx(mbar0, CHUNK_TX_BYTES);
        tma3d(smem_base + OFF_S0, &tm_second, x0 - P_, y0 - P_, cz, mbar0);
        tma3d(smem_base + OFF_F0, &tm_first,  x0,      y0,      cz, mbar0);
    }

    // accumulator pairs: p = pixel pair (2p, 2p+1), d = displacement 0..8
    u64 acc2[4][D_];
#pragma unroll
    for (int p = 0; p < 4; p++)
#pragma unroll
        for (int d = 0; d < D_; d++)
            acc2[p][d] = 0ull;

    const int s_ro = (ly + dy) * SROW + tx * XPT;   // within one channel second tile
    const int f_ro = ly * FROW + tx * XPT;          // within one channel first tile
    const int ch_s = h * CPH * SCH;                 // this half's channel offset
    const int ch_f = h * CPH * FCH;

    for (int k = 0; k < NCHUNK; k++) {
        if (tid == 0 && (k + 1) < NCHUNK) {
            const uint32_t mb = mbar0 + ((k + 1) & 1) * 8;
            const uint32_t so = ((k + 1) & 1) ? OFF_S1 : OFF_S0;
            const uint32_t fo = ((k + 1) & 1) ? OFF_F1 : OFF_F0;
            const int cz = b * C_ + (k + 1) * CC;
            mbar_expect_tx(mb, CHUNK_TX_BYTES);
            tma3d(smem_base + so, &tm_second, x0 - P_, y0 - P_, cz, mb);
            tma3d(smem_base + fo, &tm_first,  x0,      y0,      cz, mb);
        }

        mbar_wait(mbar0 + (k & 1) * 8, (k >> 1) & 1);

        const float* sb  = dyn + ((k & 1) ? OFF_S1 : OFF_S0) / 4 + ch_s + s_ro;
        const float* fbp = dyn + ((k & 1) ? OFF_F1 : OFF_F0) / 4 + ch_f + f_ro;

#pragma unroll 1
        for (int c = 0; c < CPH; c++) {
            // first: 8 pixels (dy-invariant address -> broadcast within phase)
            const float4 fa = *(const float4*)(fbp + c * FCH);
            const float4 fb = *(const float4*)(fbp + c * FCH + 4);
            const u64 fp0 = pack2(fa.x, fa.y);
            const u64 fp1 = pack2(fa.z, fa.w);
            const u64 fp2 = pack2(fb.x, fb.y);
            const u64 fp3 = pack2(fb.z, fb.w);

            // second window: w[0..15]
            const float* srow = sb + c * SCH;
            float w[16];
            *(float4*)&w[0]  = *(const float4*)&srow[0];
            *(float4*)&w[4]  = *(const float4*)&srow[4];
            *(float4*)&w[8]  = *(const float4*)&srow[8];
            *(float4*)&w[12] = *(const float4*)&srow[12];

            u64 we[8], wo[7];
#pragma unroll
            for (int e = 0; e < 8; e++) we[e] = pack2(w[2 * e], w[2 * e + 1]);
#pragma unroll
            for (int e = 0; e < 7; e++) wo[e] = pack2(w[2 * e + 1], w[2 * e + 2]);

#pragma unroll
            for (int d = 0; d < D_; d++) {
                // pair p at displacement d multiplies w-pair at offset 2p+d
                if (d & 1) {
                    acc2[0][d] = fma2(fp0, wo[(d - 1) / 2],     acc2[0][d]);
                    acc2[1][d] = fma2(fp1, wo[(d + 1) / 2],     acc2[1][d]);
                    acc2[2][d] = fma2(fp2, wo[(d + 3) / 2],     acc2[2][d]);
                    acc2[3][d] = fma2(fp3, wo[(d + 5) / 2],     acc2[3][d]);
                } else {
                    acc2[0][d] = fma2(fp0, we[d / 2],           acc2[0][d]);
                    acc2[1][d] = fma2(fp1, we[d / 2 + 1],       acc2[1][d]);
                    acc2[2][d] = fma2(fp2, we[d / 2 + 2],       acc2[2][d]);
                    acc2[3][d] = fma2(fp3, we[d / 2 + 3],       acc2[3][d]);
                }
            }
        }
        __syncthreads();   // readers done with buffer (k&1) before refill at k+2
    }

    // ---- reduce the two channel halves via smem staging (buffer 0 region) ----
    u64* stage = (u64*)dyn;            // 144 * 36 * 8 = 41472 B, fits in S0+F0
    if (h == 1) {
#pragma unroll
        for (int p = 0; p < 4; p++)
#pragma unroll
            for (int d = 0; d < D_; d++)
                stage[w144 * 36 + p * D_ + d] = acc2[p][d];
    }
    __syncthreads();

    if (h == 0) {
        const float scale = 1.0f / (float)C_;
        const int y  = y0 + ly;
        const int xo = x0 + tx * XPT;
#pragma unroll
        for (int d = 0; d < D_; d++) {
            const int ch = dy * D_ + d;
            float o[8];
#pragma unroll
            for (int p = 0; p < 4; p++) {
                float alo, ahi, blo, bhi;
                unpack2(alo, ahi, acc2[p][d]);
                unpack2(blo, bhi, stage[w144 * 36 + p * D_ + d]);
                o[2 * p]     = (alo + blo) * scale;
                o[2 * p + 1] = (ahi + bhi) * scale;
            }
            float* op = &out[(((size_t)b * ND_ + ch) * H_ + y) * W_ + xo];
            *(float4*)op       = make_float4(o[0], o[1], o[2], o[3]);
            *(float4*)(op + 4) = make_float4(o[4], o[5], o[6], o[7]);
        }
    }
}

// ---------------- host ----------------
typedef CUresult (*EncodeTiledFn)(
    CUtensorMap*, CUtensorMapDataType, cuuint32_t, void*,
    const cuuint64_t*, const cuuint64_t*, const cuuint32_t*, const cuuint32_t*,
    CUtensorMapInterleave, CUtensorMapSwizzle, CUtensorMapL2promotion,
    CUtensorMapFloatOOBfill);

static void build_map(EncodeTiledFn fn, CUtensorMap* m, const void* base,
                      uint32_t b0, uint32_t b1, uint32_t b2)
{
    cuuint64_t dims[3]    = {(cuuint64_t)W_, (cuuint64_t)H_, (cuuint64_t)(B_ * C_)};
    cuuint64_t strides[2] = {(cuuint64_t)W_ * 4, (cuuint64_t)W_ * H_ * 4};
    cuuint32_t box[3]     = {b0, b1, b2};
    cuuint32_t es[3]      = {1, 1, 1};
    fn(m, CU_TENSOR_MAP_DATA_TYPE_FLOAT32, 3, (void*)base,
       dims, strides, box, es,
       CU_TENSOR_MAP_INTERLEAVE_NONE, CU_TENSOR_MAP_SWIZZLE_NONE,
       CU_TENSOR_MAP_L2_PROMOTION_L2_128B, CU_TENSOR_MAP_FLOAT_OOB_FILL_NONE);
}

extern "C" void kernel_launch(void* const* d_in, const int* in_sizes, int n_in,
                              void* d_out, int out_size)
{
    const float* first  = (const float*)d_in[0];
    const float* second = (const float*)d_in[1];
    float* out = (float*)d_out;

    void* fp = nullptr;
    cudaDriverEntryPointQueryResult st;
    cudaGetDriverEntryPoint("cuTensorMapEncodeTiled", &fp, cudaEnableDefault, &st);
    EncodeTiledFn enc = (EncodeTiledFn)fp;

    CUtensorMap tm_first, tm_second;
    build_map(enc, &tm_first,  first,  FROW, YT, CC);   // box (32, 4, 16)
    build_map(enc, &tm_second, second, SWID, SH, CC);   // box (44, 12, 16)

    cudaFuncSetAttribute(corr_kernel,
                         cudaFuncAttributeMaxDynamicSharedMemorySize, SMEM_TOTAL);

    dim3 grid(W_ / TX, H_ / YT, B_);   // (7, 32, 4) = 896 blocks
    dim3 block(NTHR);                  // 288
    corr_kernel<<<grid, block, SMEM_TOTAL>>>(tm_first, tm_second, out);
}

// round 15
// speedup vs baseline: 1.0003x; 1.0003x over previous
#include <cuda_runtime.h>
#include <cuda.h>
#include <cuda_bf16.h>
#include <cstdint>

// Correlation layer (FlowNet-style), MAX_DISP=4.
// first, second: (B=4, C=256, H=128, W=224) fp32 NCHW
// out: (B, 81, H, W) fp32
//
// R12: XPT=8 + pixel-paired fma.rn.f32x2.
//      Threads = (tx4, dy9, ly4, csplit2) = 288, all active.
//      TMA double buffer, CC=16 (each half does 8 ch/chunk), SROW=44
//      (conflict-free), end-of-kernel smem reduction across the c-halves.

#define B_   4
#define C_   256
#define H_   128
#define W_   224
#define P_   4
#define D_   9      // 2P+1
#define ND_  81

#define TX    32    // x-tile width (224 = 7*32)
#define YT    4     // y rows per block
#define XPT   8     // x pixels per thread
#define XT    4     // x-thread count (32/8)
#define CC    16    // channels per chunk (8 per c-half)
#define CPH   8     // channels per half
#define NCHUNK (C_ / CC)   // 16

#define SWID  44    // second TMA box width: 8 halo + 32 + 4 right pad (OOB zero)
#define SROW  44    // == box width (dense TMA rows); 44 % 32 == 12 -> conflict-free
#define SH    12    // second rows incl. halo (4+8)
#define FROW  32

#define SCH   (SH * SROW)        // 528 floats per channel (second)
#define FCH   (YT * FROW)        // 128 floats per channel (first)
#define SBUF_FLOATS (CC * SCH)   // 8448
#define FBUF_FLOATS (CC * FCH)   // 2048
#define SBUF_BYTES  (SBUF_FLOATS * 4)   // 33792
#define FBUF_BYTES  (FBUF_FLOATS * 4)   // 8192
// layout: [S0][F0][S1][F1][mbar]  (buffer0 contiguous -> reusable as staging)
#define OFF_S0   0
#define OFF_F0   SBUF_BYTES
#define OFF_S1   (SBUF_BYTES + FBUF_BYTES)
#define OFF_F1   (2 * SBUF_BYTES + FBUF_BYTES)
#define OFF_MBAR (2 * SBUF_BYTES + 2 * FBUF_BYTES)   // 83968
#define SMEM_TOTAL (OFF_MBAR + 64)

#define CHUNK_TX_BYTES (SBUF_BYTES + FBUF_BYTES)     // 41984

#define NTHR 288    // 4 * 9 * 4 * 2, every thread is a worker
typedef unsigned long long u64;

// ---------------- device-side PTX helpers ----------------
__device__ __forceinline__ uint32_t smem_u32(const void* p) {
    return (uint32_t)__cvta_generic_to_shared(p);
}
__device__ __forceinline__ void mbar_init(uint32_t a, uint32_t cnt) {
    asm volatile("mbarrier.init.shared.b64 [%0], %1;" :: "r"(a), "r"(cnt) : "memory");
}
__device__ __forceinline__ void mbar_expect_tx(uint32_t a, uint32_t bytes) {
    asm volatile("mbarrier.arrive.expect_tx.shared.b64 _, [%0], %1;"
                 :: "r"(a), "r"(bytes) : "memory");
}
__device__ __forceinline__ void mbar_wait(uint32_t a, uint32_t parity) {
    uint32_t done;
    asm volatile(
        "{\n\t.reg .pred p;\n\t"
        "mbarrier.try_wait.parity.acquire.cta.shared::cta.b64 p, [%1], %2;\n\t"
        "selp.b32 %0, 1, 0, p;\n\t}"
        : "=r"(done) : "r"(a), "r"(parity) : "memory");
    if (!done) {
        asm volatile(
            "{\n\t.reg .pred P1;\n\t"
            "WL_%=:\n\t"
            "mbarrier.try_wait.parity.acquire.cta.shared::cta.b64 P1, [%0], %1, 0x989680;\n\t"
            "@P1 bra.uni WD_%=;\n\t"
            "bra.uni WL_%=;\n\t"
            "WD_%=:\n\t}"
            :: "r"(a), "r"(parity) : "memory");
    }
}
__device__ __forceinline__ void tma3d(uint32_t smem_dst, const CUtensorMap* tmap,
                                      int cx, int cy, int cz, uint32_t mbar) {
    asm volatile(
        "cp.async.bulk.tensor.3d.shared::cta.global.tile.mbarrier::complete_tx::bytes "
        "[%0], [%1, {%2, %3, %4}], [%5];"
        :: "r"(smem_dst), "l"(tmap), "r"(cx), "r"(cy), "r"(cz), "r"(mbar)
        : "memory");
}
__device__ __forceinline__ u64 pack2(float lo, float hi) {
    u64 r;
    asm("mov.b64 %0, {%1, %2};" : "=l"(r) : "f"(lo), "f"(hi));
    return r;
}
__device__ __forceinline__ void unpack2(float& lo, float& hi, u64 v) {
    asm("mov.b64 {%0, %1}, %2;" : "=f"(lo), "=f"(hi) : "l"(v));
}
__device__ __forceinline__ u64 fma2(u64 a, u64 b, u64 c) {
    u64 r;
    asm("fma.rn.f32x2 %0, %1, %2, %3;" : "=l"(r) : "l"(a), "l"(b), "l"(c));
    return r;
}

// ---------------- kernel ----------------
__global__ __launch_bounds__(NTHR, 2)
void corr_kernel(const __grid_constant__ CUtensorMap tm_first,
                 const __grid_constant__ CUtensorMap tm_second,
                 float* __restrict__ out)
{
    extern __shared__ float dyn[];
    const uint32_t smem_base = smem_u32(dyn);
    const uint32_t mbar0 = smem_base + OFF_MBAR;

    const int xt = blockIdx.x;          // 0..6
    const int y0 = blockIdx.y * YT;     // 0..124
    const int b  = blockIdx.z;          // 0..3
    const int x0 = xt * TX;

    const int tid = threadIdx.x;        // 0..287
    const int tx  = tid & 3;            // 0..3
    const int dy  = (tid >> 2) % D_;    // 0..8
    const int ly  = (tid / (XT * D_)) & 3;  // 0..3
    const int h   = tid / (XT * D_ * YT);   // 0..1  (channel half)
    const int w144 = tid % (XT * D_ * YT);  // id within a half, 0..143

    if (tid == 0) {
        mbar_init(mbar0, 1);
        mbar_init(mbar0 + 8, 1);
    }
    __syncthreads();

    // prefetch chunk 0 into buffer 0
    if (tid == 0) {
        const int cz = b * C_;
        mbar_expect_tx(mbar0, CHUNK_TX_BYTES);
        tma3d(smem_base + OFF_S0, &tm_second, x0 - P_, y0 - P_, cz, mbar0);
        tma3d(smem_base + OFF_F0, &tm_first,  x0,      y0,      cz, mbar0);
    }

    // accumulator pairs: p = pixel pair (2p, 2p+1), d = displacement 0..8
    u64 acc2[4][D_];
#pragma unroll
    for (int p = 0; p < 4; p++)
#pragma unroll
        for (int d = 0; d < D_; d++)
            acc2[p][d] = 0ull;

    const int s_ro = (ly + dy) * SROW + tx * XPT;   // within one channel second tile
    const int f_ro = ly * FROW + tx * XPT;          // within one channel first tile
    const int ch_s = h * CPH * SCH;                 // this half's channel offset
    const int ch_f = h * CPH * FCH;

    for (int k = 0; k < NCHUNK; k++) {
        if (tid == 0 && (k + 1) < NCHUNK) {
            const uint32_t mb = mbar0 + ((k + 1) & 1) * 8;
            const uint32_t so = ((k + 1) & 1) ? OFF_S1 : OFF_S0;
            const uint32_t fo = ((k + 1) & 1) ? OFF_F1 : OFF_F0;
            const int cz = b * C_ + (k + 1) * CC;
            mbar_expect_tx(mb, CHUNK_TX_BYTES);
            tma3d(smem_base + so, &tm_second, x0 - P_, y0 - P_, cz, mb);
            tma3d(smem_base + fo, &tm_first,  x0,      y0,      cz, mb);
        }

        mbar_wait(mbar0 + (k & 1) * 8, (k >> 1) & 1);

        const float* sb  = dyn + ((k & 1) ? OFF_S1 : OFF_S0) / 4 + ch_s + s_ro;
        const float* fbp = dyn + ((k & 1) ? OFF_F1 : OFF_F0) / 4 + ch_f + f_ro;

#pragma unroll 1
        for (int c = 0; c < CPH; c++) {
            // first: 8 pixels (dy-invariant address -> broadcast within phase)
            const float4 fa = *(const float4*)(fbp + c * FCH);
            const float4 fb = *(const float4*)(fbp + c * FCH + 4);
            const u64 fp0 = pack2(fa.x, fa.y);
            const u64 fp1 = pack2(fa.z, fa.w);
            const u64 fp2 = pack2(fb.x, fb.y);
            const u64 fp3 = pack2(fb.z, fb.w);

            // second window: w[0..15]
            const float* srow = sb + c * SCH;
            float w[16];
            *(float4*)&w[0]  = *(const float4*)&srow[0];
            *(float4*)&w[4]  = *(const float4*)&srow[4];
            *(float4*)&w[8]  = *(const float4*)&srow[8];
            *(float4*)&w[12] = *(const float4*)&srow[12];

            u64 we[8], wo[7];
#pragma unroll
            for (int e = 0; e < 8; e++) we[e] = pack2(w[2 * e], w[2 * e + 1]);
#pragma unroll
            for (int e = 0; e < 7; e++) wo[e] = pack2(w[2 * e + 1], w[2 * e + 2]);

#pragma unroll
            for (int d = 0; d < D_; d++) {
                // pair p at displacement d multiplies w-pair at offset 2p+d
                if (d & 1) {
                    acc2[0][d] = fma2(fp0, wo[(d - 1) / 2],     acc2[0][d]);
                    acc2[1][d] = fma2(fp1, wo[(d + 1) / 2],     acc2[1][d]);
                    acc2[2][d] = fma2(fp2, wo[(d + 3) / 2],     acc2[2][d]);
                    acc2[3][d] = fma2(fp3, wo[(d + 5) / 2],     acc2[3][d]);
                } else {
                    acc2[0][d] = fma2(fp0, we[d / 2],           acc2[0][d]);
                    acc2[1][d] = fma2(fp1, we[d / 2 + 1],       acc2[1][d]);
                    acc2[2][d] = fma2(fp2, we[d / 2 + 2],       acc2[2][d]);
                    acc2[3][d] = fma2(fp3, we[d / 2 + 3],       acc2[3][d]);
                }
            }
        }
        __syncthreads();   // readers done with buffer (k&1) before refill at k+2
    }

    // ---- reduce the two channel halves via smem staging (buffer 0 region) ----
    u64* stage = (u64*)dyn;            // 144 * 36 * 8 = 41472 B, fits in S0+F0
    if (h == 1) {
#pragma unroll
        for (int p = 0; p < 4; p++)
#pragma unroll
            for (int d = 0; d < D_; d++)
                stage[w144 * 36 + p * D_ + d] = acc2[p][d];
    }
    __syncthreads();

    if (h == 0) {
        const float scale = 1.0f / (float)C_;
        const int y  = y0 + ly;
        const int xo = x0 + tx * XPT;
#pragma unroll
        for (int d = 0; d < D_; d++) {
            const int ch = dy * D_ + d;
            float o[8];
#pragma unroll
            for (int p = 0; p < 4; p++) {
                float alo, ahi, blo, bhi;
                unpack2(alo, ahi, acc2[p][d]);
                unpack2(blo, bhi, stage[w144 * 36 + p * D_ + d]);
                o[2 * p]     = (alo + blo) * scale;
                o[2 * p + 1] = (ahi + bhi) * scale;
            }
            float* op = &out[(((size_t)b * ND_ + ch) * H_ + y) * W_ + xo];
            *(float4*)op       = make_float4(o[0], o[1], o[2], o[3]);
            *(float4*)(op + 4) = make_float4(o[4], o[5], o[6], o[7]);
        }
    }
}

// ---------------- host ----------------
typedef CUresult (*EncodeTiledFn)(
    CUtensorMap*, CUtensorMapDataType, cuuint32_t, void*,
    const cuuint64_t*, const cuuint64_t*, const cuuint32_t*, const cuuint32_t*,
    CUtensorMapInterleave, CUtensorMapSwizzle, CUtensorMapL2promotion,
    CUtensorMapFloatOOBfill);

static void build_map(EncodeTiledFn fn, CUtensorMap* m, const void* base,
                      uint32_t b0, uint32_t b1, uint32_t b2)
{
    cuuint64_t dims[3]    = {(cuuint64_t)W_, (cuuint64_t)H_, (cuuint64_t)(B_ * C_)};
    cuuint64_t strides[2] = {(cuuint64_t)W_ * 4, (cuuint64_t)W_ * H_ * 4};
    cuuint32_t box[3]     = {b0, b1, b2};
    cuuint32_t es[3]      = {1, 1, 1};
    fn(m, CU_TENSOR_MAP_DATA_TYPE_FLOAT32, 3, (void*)base,
       dims, strides, box, es,
       CU_TENSOR_MAP_INTERLEAVE_NONE, CU_TENSOR_MAP_SWIZZLE_NONE,
       CU_TENSOR_MAP_L2_PROMOTION_L2_128B, CU_TENSOR_MAP_FLOAT_OOB_FILL_NONE);
}

extern "C" void kernel_launch(void* const* d_in, const int* in_sizes, int n_in,
                              void* d_out, int out_size)
{
    const float* first  = (const float*)d_in[0];
    const float* second = (const float*)d_in[1];
    float* out = (float*)d_out;

    void* fp = nullptr;
    cudaDriverEntryPointQueryResult st;
    cudaGetDriverEntryPoint("cuTensorMapEncodeTiled", &fp, cudaEnableDefault, &st);
    EncodeTiledFn enc = (EncodeTiledFn)fp;

    CUtensorMap tm_first, tm_second;
    build_map(enc, &tm_first,  first,  FROW, YT, CC);   // box (32, 4, 16)
    build_map(enc, &tm_second, second, SWID, SH, CC);   // box (44, 12, 16)

    cudaFuncSetAttribute(corr_kernel,
                         cudaFuncAttributeMaxDynamicSharedMemorySize, SMEM_TOTAL);

    dim3 grid(W_ / TX, H_ / YT, B_);   // (7, 32, 4) = 896 blocks
    dim3 block(NTHR);                  // 288
    corr_kernel<<<grid, block, SMEM_TOTAL>>>(tm_first, tm_second, out);
}